// round 5
// baseline (speedup 1.0000x reference)
#include <cuda_runtime.h>

// BeliefMatchingLoss: pred [8,19,512,512] f32, target [8,512,512] int32 -> scalar f32
// Single-kernel last-block reduction; self-resetting for graph replay.
//
// loss_pix = 0.01*( lnG(a0) - (a0-19)*psi(a0) + sum_c g(a_c) ) + psi(a0) - psi(a_ans)
// g(x) via shift-2 (z=x+2, P=x(x+1), one rcp gives 1/z and S=Pp/P since Pp*z=2P+3x+2):
//   g = lnP - 2.5*lnz - (x-1)*c(z) - (x-1)*S - t(z) + z - 0.5*ln(2pi)
// RCP batched in class-pairs (short live ranges -> 64 regs / 4 CTAs per SM),
// LG2 of P batched over 4 classes, LG2 of z over 8. Packed 2 pixels/thread
// with fma.rn.f32x2. Answer class: select scalar x only; recompute psi at end.

typedef unsigned long long u64;

#define HW_   (512 * 512)
#define NC_   19
#define NPIX_ (8 * HW_)
#define NTHR_ (NPIX_ / 2)
#define NBLK_ (NTHR_ / 256)

#define LN2F        0.6931471805599453f
#define LOG2EF      1.4426950408889634f
#define HALF_LN_2PI 0.91893853320467274f

__device__ double             g_sum    = 0.0;
__device__ unsigned long long g_cnt    = 0ull;
__device__ unsigned int       g_arrive = 0u;

// ---- packed f32x2 helpers (u64 = {lo,hi} fp32 pair) ----
__device__ __forceinline__ u64 pk2(float a, float b) {
    u64 r; asm("mov.b64 %0,{%1,%2};" : "=l"(r) : "f"(a), "f"(b)); return r;
}
__device__ __forceinline__ void upk2(u64 v, float& a, float& b) {
    asm("mov.b64 {%0,%1},%2;" : "=f"(a), "=f"(b) : "l"(v));
}
__device__ __forceinline__ u64 f2fma(u64 a, u64 b, u64 c) {
    u64 d; asm("fma.rn.f32x2 %0,%1,%2,%3;" : "=l"(d) : "l"(a), "l"(b), "l"(c)); return d;
}
__device__ __forceinline__ u64 f2mul(u64 a, u64 b) {
    u64 d; asm("mul.rn.f32x2 %0,%1,%2;" : "=l"(d) : "l"(a), "l"(b)); return d;
}
__device__ __forceinline__ u64 f2add(u64 a, u64 b) {
    u64 d; asm("add.rn.f32x2 %0,%1,%2;" : "=l"(d) : "l"(a), "l"(b)); return d;
}
__device__ __forceinline__ float ex2f(float x) { float r; asm("ex2.approx.f32 %0,%1;" : "=f"(r) : "f"(x)); return r; }
__device__ __forceinline__ float lg2f_(float x){ float r; asm("lg2.approx.f32 %0,%1;" : "=f"(r) : "f"(x)); return r; }
__device__ __forceinline__ float rcpf_(float x){ float r; asm("rcp.approx.f32 %0,%1;" : "=f"(r) : "f"(x)); return r; }
__device__ __forceinline__ u64 rcp_2(u64 v) { float a, b; upk2(v, a, b); return pk2(rcpf_(a), rcpf_(b)); }

// scalar digamma+lgamma, shift-2 (once per pixel on a0)
__device__ __forceinline__ void psi_lg_s(float x, float& psi, float& lg) {
    float z   = x + 2.0f;
    float P   = fmaf(x, x, x);
    float r   = rcpf_(P * z);
    float S   = fmaf(2.0f, P, fmaf(3.0f, x, 2.0f)) * r;  // Pp/P
    float rz  = P * r;                                   // 1/z
    float rz2 = rz * rz;
    float lnz = lg2f_(z) * LN2F;
    float lnP = lg2f_(P) * LN2F;
    float c = fmaf(rz, 0.5f, rz2 * fmaf(rz2, -1.0f / 120.0f, 1.0f / 12.0f));
    float t = rz * fmaf(rz2, -1.0f / 360.0f, 1.0f / 12.0f);
    psi = lnz - c - S;
    lg  = fmaf(z - 0.5f, lnz, -z) + HALF_LN_2PI + t - lnP;
}

// scalar digamma only, shift-2 (once per pixel on x_ans)
__device__ __forceinline__ float psi_s(float x) {
    float z   = x + 2.0f;
    float P   = fmaf(x, x, x);
    float r   = rcpf_(P * z);
    float S   = fmaf(2.0f, P, fmaf(3.0f, x, 2.0f)) * r;
    float rz  = P * r;
    float rz2 = rz * rz;
    float c = fmaf(rz, 0.5f, rz2 * fmaf(rz2, -1.0f / 120.0f, 1.0f / 12.0f));
    return lg2f_(z) * LN2F - c - S;
}

__global__ __launch_bounds__(256, 4) void bml_main(const float* __restrict__ pred,
                                                   const int*  __restrict__ tgt,
                                                   float*      __restrict__ out) {
    int tix = blockIdx.x * 256 + threadIdx.x;
    int pix = tix * 2;
    int b   = pix >> 18;
    int hw  = pix & (HW_ - 1);
    const float* pp = pred + (size_t)b * NC_ * HW_ + hw;

    int2 tv  = *reinterpret_cast<const int2*>(tgt + pix);
    bool ig0 = (tv.x == 255), ig1 = (tv.y == 255);
    int  ta0 = ig0 ? 0 : tv.x;
    int  ta1 = ig1 ? 0 : tv.y;

    const u64 K1    = pk2(1.0f, 1.0f);
    const u64 K2    = pk2(2.0f, 2.0f);
    const u64 K3    = pk2(3.0f, 3.0f);
    const u64 KH    = pk2(0.5f, 0.5f);
    const u64 Km1   = pk2(-1.0f, -1.0f);
    const u64 K12   = pk2(1.0f / 12.0f, 1.0f / 12.0f);
    const u64 Km120 = pk2(-1.0f / 120.0f, -1.0f / 120.0f);
    const u64 Km360 = pk2(-1.0f / 360.0f, -1.0f / 360.0f);

    u64 accW = pk2(0.0f, 0.0f), accT = accW, a0v = accW;
    u64 zp = K1, Pacc = K1;
    float lgp_lo = 0.0f, lgp_hi = 0.0f;   // sum lg2(P) per pixel
    float lgz_lo = 0.0f, lgz_hi = 0.0f;   // sum lg2(z) per pixel
    float xa0 = 1.0f, xa1 = 1.0f;         // alpha at answer class

    // STAGE1: load, exp, select answer-x, derive z/P/Q
#define STAGE1(xx, zz, PP, QQ, c) do {                                        \
        float2 pv = *reinterpret_cast<const float2*>(pp + (size_t)(c) * HW_); \
        float xl = ex2f(pv.x * LOG2EF);                                       \
        float xh = ex2f(pv.y * LOG2EF);                                       \
        if ((c) == ta0) xa0 = xl;                                             \
        if ((c) == ta1) xa1 = xh;                                             \
        (xx) = pk2(xl, xh);                                                   \
        (zz) = f2add((xx), K2);                                               \
        (PP) = f2fma((xx), (xx), (xx));                                       \
        (QQ) = f2mul((PP), (zz));                                             \
    } while (0)

    // STAGE2: series terms + accumulators (r = 1/(P*z))
#define STAGE2(xx, PP, rr) do {                                               \
        u64 rz  = f2mul((PP), (rr));                                          \
        u64 S   = f2mul(f2fma(K2, (PP), f2fma(K3, (xx), K2)), (rr));          \
        u64 rz2 = f2mul(rz, rz);                                              \
        u64 v_  = f2mul(rz2, f2fma(rz2, Km120, K12));                         \
        u64 cs  = f2add(f2fma(rz, KH, v_), S);                                \
        u64 tt  = f2mul(rz, f2fma(rz2, Km360, K12));                          \
        u64 xm1 = f2add((xx), Km1);                                           \
        accW = f2fma(xm1, cs, accW);                                          \
        accT = f2add(accT, tt);                                               \
        a0v  = f2add(a0v, (xx));                                              \
    } while (0)

#pragma unroll
    for (int k = 0; k < 9; ++k) {
        const int c0 = 2 * k, c1 = 2 * k + 1;
        u64 x0, z0, P0, Q0, x1, z1, P1, Q1;
        STAGE1(x0, z0, P0, Q0, c0);
        STAGE1(x1, z1, P1, Q1, c1);
        u64 rr = rcp_2(f2mul(Q0, Q1));         // 1/(Q0*Q1), one rcp per pixel
        u64 r0 = f2mul(rr, Q1);
        u64 r1 = f2mul(rr, Q0);
        zp   = f2mul(zp, f2mul(z0, z1));       // z dead after this
        Pacc = f2mul(Pacc, f2mul(P0, P1));
        if (k & 1) {                            // lg2 of 4-class P product
            float pl, ph; upk2(Pacc, pl, ph);
            lgp_lo += lg2f_(pl); lgp_hi += lg2f_(ph);
            Pacc = K1;
        }
        if (k == 3 || k == 7) {                 // lg2 of 8-class z product
            float zl, zh; upk2(zp, zl, zh);
            lgz_lo += lg2f_(zl); lgz_hi += lg2f_(zh);
            zp = K1;
        }
        STAGE2(x0, P0, r0);
        STAGE2(x1, P1, r1);
    }
    { // tail class 18
        u64 x0, z0, P0, Q0;
        STAGE1(x0, z0, P0, Q0, 18);
        u64 r0 = rcp_2(Q0);
        zp   = f2mul(zp, z0);
        Pacc = f2mul(Pacc, P0);
        float pl, ph, zl, zh;
        upk2(Pacc, pl, ph);
        lgp_lo += lg2f_(pl); lgp_hi += lg2f_(ph);
        upk2(zp, zl, zh);
        lgz_lo += lg2f_(zl); lgz_hi += lg2f_(zh);
        STAGE2(x0, P0, r0);
    }
#undef STAGE1
#undef STAGE2

    float aW_lo, aW_hi, aT_lo, aT_hi, a0_lo, a0_hi;
    upk2(accW, aW_lo, aW_hi);
    upk2(accT, aT_lo, aT_hi);
    upk2(a0v,  a0_lo, a0_hi);

    const float KADD = 38.0f - 19.0f * HALF_LN_2PI;

    float sumg_lo = fmaf(LN2F, lgp_lo, fmaf(-2.5f * LN2F, lgz_lo, -aW_lo - aT_lo)) + a0_lo + KADD;
    float psi0_lo, lg0_lo;
    psi_lg_s(a0_lo, psi0_lo, lg0_lo);
    float psia_lo = psi_s(xa0);
    float kl_lo   = fmaf(-(a0_lo - 19.0f), psi0_lo, lg0_lo) + sumg_lo;
    float loss_lo = fmaf(0.01f, kl_lo, psi0_lo - psia_lo);
    if (ig0) loss_lo = 0.0f;

    float sumg_hi = fmaf(LN2F, lgp_hi, fmaf(-2.5f * LN2F, lgz_hi, -aW_hi - aT_hi)) + a0_hi + KADD;
    float psi0_hi, lg0_hi;
    psi_lg_s(a0_hi, psi0_hi, lg0_hi);
    float psia_hi = psi_s(xa1);
    float kl_hi   = fmaf(-(a0_hi - 19.0f), psi0_hi, lg0_hi) + sumg_hi;
    float loss_hi = fmaf(0.01f, kl_hi, psi0_hi - psia_hi);
    if (ig1) loss_hi = 0.0f;

    float loss  = loss_lo + loss_hi;
    int   valid = (ig0 ? 0 : 1) + (ig1 ? 0 : 1);

#pragma unroll
    for (int o = 16; o; o >>= 1) {
        loss  += __shfl_down_sync(0xffffffffu, loss, o);
        valid += __shfl_down_sync(0xffffffffu, valid, o);
    }

    __shared__ float s_l[8];
    __shared__ int   s_v[8];
    int wid = threadIdx.x >> 5;
    int lid = threadIdx.x & 31;
    if (lid == 0) { s_l[wid] = loss; s_v[wid] = valid; }
    __syncthreads();

    if (threadIdx.x == 0) {
        float L = 0.0f;
        int   V = 0;
#pragma unroll
        for (int w = 0; w < 8; ++w) { L += s_l[w]; V += s_v[w]; }
        atomicAdd(&g_sum, (double)L);
        atomicAdd(&g_cnt, (unsigned long long)V);
        __threadfence();
        unsigned int n = atomicAdd(&g_arrive, 1u);
        if (n == (unsigned int)(NBLK_ - 1)) {
            __threadfence();
            double s = *((volatile double*)&g_sum);
            unsigned long long c = *((volatile unsigned long long*)&g_cnt);
            out[0] = (float)(s / (double)c);
            g_sum    = 0.0;
            g_cnt    = 0ull;
            g_arrive = 0u;
        }
    }
}

extern "C" void kernel_launch(void* const* d_in, const int* in_sizes, int n_in,
                              void* d_out, int out_size) {
    const float* pred = (const float*)d_in[0];
    const int*   tgt  = (const int*)d_in[1];
    float*       out  = (float*)d_out;

    bml_main<<<NBLK_, 256>>>(pred, tgt, out);
}

// round 6
// speedup vs baseline: 1.3687x; 1.3687x over previous
#include <cuda_runtime.h>

// BeliefMatchingLoss: pred [8,19,512,512] f32, target [8,512,512] int32 -> scalar f32
// Single-kernel last-block reduction; self-resetting for graph replay.
//
// loss_pix = 0.01*( lnG(a0) - (a0-19)*psi(a0) + sum_c g(a_c) ) + psi(a0) - psi(a_ans)
// g(x) with shift-2 (z=x+2, P=x(x+1), u=1/z, r=1/(Pz) -> u=P*r, 1/P=z*r):
//   g = lnP - 2.5*lnz - poly(u) + (3x+1)/P + z - (2.5 + 0.5*ln(2pi))
//   poly(u) = u*(-4/3 + u*(-1/4 + u*(-1/90 + u/40)))   [= (x-1)c(z)+t(z) - 1/2]
//   (the (x-1)*S term folds to 2 - (3x+1)/P exactly)
// Answer class handled by a 4B gather + scalar psi recompute (no per-class selects).
// RCP batched per class-pair; LG2 of P over 4 classes, of z over 8.
// All packed 2 pixels/thread via fma.rn.f32x2.

typedef unsigned long long u64;

#define HW_   (512 * 512)
#define NC_   19
#define NPIX_ (8 * HW_)
#define NTHR_ (NPIX_ / 2)
#define NBLK_ (NTHR_ / 256)

#define LN2F        0.6931471805599453f
#define LOG2EF      1.4426950408889634f
#define HALF_LN_2PI 0.91893853320467274f

__device__ double             g_sum    = 0.0;
__device__ unsigned long long g_cnt    = 0ull;
__device__ unsigned int       g_arrive = 0u;

// ---- packed f32x2 helpers (u64 = {lo,hi} fp32 pair) ----
__device__ __forceinline__ u64 pk2(float a, float b) {
    u64 r; asm("mov.b64 %0,{%1,%2};" : "=l"(r) : "f"(a), "f"(b)); return r;
}
__device__ __forceinline__ void upk2(u64 v, float& a, float& b) {
    asm("mov.b64 {%0,%1},%2;" : "=f"(a), "=f"(b) : "l"(v));
}
__device__ __forceinline__ u64 f2fma(u64 a, u64 b, u64 c) {
    u64 d; asm("fma.rn.f32x2 %0,%1,%2,%3;" : "=l"(d) : "l"(a), "l"(b), "l"(c)); return d;
}
__device__ __forceinline__ u64 f2mul(u64 a, u64 b) {
    u64 d; asm("mul.rn.f32x2 %0,%1,%2;" : "=l"(d) : "l"(a), "l"(b)); return d;
}
__device__ __forceinline__ u64 f2add(u64 a, u64 b) {
    u64 d; asm("add.rn.f32x2 %0,%1,%2;" : "=l"(d) : "l"(a), "l"(b)); return d;
}
__device__ __forceinline__ float ex2f(float x) { float r; asm("ex2.approx.f32 %0,%1;" : "=f"(r) : "f"(x)); return r; }
__device__ __forceinline__ float lg2f_(float x){ float r; asm("lg2.approx.f32 %0,%1;" : "=f"(r) : "f"(x)); return r; }
__device__ __forceinline__ float rcpf_(float x){ float r; asm("rcp.approx.f32 %0,%1;" : "=f"(r) : "f"(x)); return r; }
__device__ __forceinline__ u64 rcp_2(u64 v) { float a, b; upk2(v, a, b); return pk2(rcpf_(a), rcpf_(b)); }

// scalar digamma+lgamma, shift-2 (once per pixel on a0 >= 19)
__device__ __forceinline__ void psi_lg_s(float x, float& psi, float& lg) {
    float z   = x + 2.0f;
    float P   = fmaf(x, x, x);
    float r   = rcpf_(P * z);
    float S   = fmaf(2.0f, P, fmaf(3.0f, x, 2.0f)) * r;
    float rz  = P * r;
    float rz2 = rz * rz;
    float lnz = lg2f_(z) * LN2F;
    float lnP = lg2f_(P) * LN2F;
    float c = fmaf(rz, 0.5f, rz2 * fmaf(rz2, -1.0f / 120.0f, 1.0f / 12.0f));
    float t = rz * fmaf(rz2, -1.0f / 360.0f, 1.0f / 12.0f);
    psi = lnz - c - S;
    lg  = fmaf(z - 0.5f, lnz, -z) + HALF_LN_2PI + t - lnP;
}

// scalar digamma only (once per pixel on x_ans)
__device__ __forceinline__ float psi_s(float x) {
    float z   = x + 2.0f;
    float P   = fmaf(x, x, x);
    float r   = rcpf_(P * z);
    float S   = fmaf(2.0f, P, fmaf(3.0f, x, 2.0f)) * r;
    float rz  = P * r;
    float rz2 = rz * rz;
    float c = fmaf(rz, 0.5f, rz2 * fmaf(rz2, -1.0f / 120.0f, 1.0f / 12.0f));
    return lg2f_(z) * LN2F - c - S;
}

__global__ __launch_bounds__(256, 4) void bml_main(const float* __restrict__ pred,
                                                   const int*  __restrict__ tgt,
                                                   float*      __restrict__ out) {
    int tix = blockIdx.x * 256 + threadIdx.x;
    int pix = tix * 2;
    int b   = pix >> 18;
    int hw  = pix & (HW_ - 1);
    const float* pp = pred + (size_t)b * NC_ * HW_ + hw;

    int2 tv  = *reinterpret_cast<const int2*>(tgt + pix);
    bool ig0 = (tv.x == 255), ig1 = (tv.y == 255);
    int  ta0 = ig0 ? 0 : tv.x;
    int  ta1 = ig1 ? 0 : tv.y;

    // answer-class gather (no per-class selects in the main loop)
    float pa0 = pp[(size_t)ta0 * HW_];
    float pa1 = pp[(size_t)ta1 * HW_ + 1];

    const u64 KL2E = pk2(LOG2EF, LOG2EF);
    const u64 K1   = pk2(1.0f, 1.0f);
    const u64 K2   = pk2(2.0f, 2.0f);
    const u64 K3   = pk2(3.0f, 3.0f);
    const u64 C40  = pk2(1.0f / 40.0f, 1.0f / 40.0f);
    const u64 Cm90 = pk2(-1.0f / 90.0f, -1.0f / 90.0f);
    const u64 Cm4  = pk2(-0.25f, -0.25f);
    const u64 Cm43 = pk2(-4.0f / 3.0f, -4.0f / 3.0f);

    u64 accP = pk2(0.0f, 0.0f);   // sum poly(u)
    u64 acc2 = accP;              // sum (3x+1)/P
    u64 a0v  = accP;              // sum x
    u64 zp = K1, Pacc = K1;
    float lgp_lo = 0.0f, lgp_hi = 0.0f;   // sum lg2(P)
    float lgz_lo = 0.0f, lgz_hi = 0.0f;   // sum lg2(z)

#define STAGE1(xx, zz, PP, QQ, c) do {                                        \
        u64 pv = *reinterpret_cast<const u64*>(pp + (size_t)(c) * HW_);       \
        u64 e  = f2mul(pv, KL2E);                                             \
        float el, eh; upk2(e, el, eh);                                        \
        (xx) = pk2(ex2f(el), ex2f(eh));                                       \
        (zz) = f2add((xx), K2);                                               \
        (PP) = f2fma((xx), (xx), (xx));                                       \
        (QQ) = f2mul((PP), (zz));                                             \
    } while (0)

#define STAGE2(xx, zz, PP, rr) do {                                           \
        u64 u_ = f2mul((PP), (rr));            /* 1/z  */                     \
        u64 ip = f2mul((zz), (rr));            /* 1/P  */                     \
        u64 q  = f2fma(u_, C40, Cm90);                                        \
        q      = f2fma(u_, q, Cm4);                                           \
        q      = f2fma(u_, q, Cm43);                                          \
        accP   = f2fma(u_, q, accP);                                          \
        u64 w  = f2fma(K3, (xx), K1);          /* 3x+1 */                     \
        acc2   = f2fma(w, ip, acc2);                                          \
        a0v    = f2add(a0v, (xx));                                            \
    } while (0)

#pragma unroll
    for (int k = 0; k < 9; ++k) {
        const int c0 = 2 * k, c1 = 2 * k + 1;
        u64 x0, z0, P0, Q0, x1, z1, P1, Q1;
        STAGE1(x0, z0, P0, Q0, c0);
        STAGE1(x1, z1, P1, Q1, c1);
        u64 rr = rcp_2(f2mul(Q0, Q1));
        u64 r0 = f2mul(rr, Q1);
        u64 r1 = f2mul(rr, Q0);
        zp   = f2mul(zp, f2mul(z0, z1));
        Pacc = f2mul(Pacc, f2mul(P0, P1));
        if (k & 1) {                            // 4-class lnP batch
            float pl, ph; upk2(Pacc, pl, ph);
            lgp_lo += lg2f_(pl); lgp_hi += lg2f_(ph);
            Pacc = K1;
        }
        if (k == 3 || k == 7) {                 // 8-class lnz batch
            float zl, zh; upk2(zp, zl, zh);
            lgz_lo += lg2f_(zl); lgz_hi += lg2f_(zh);
            zp = K1;
        }
        STAGE2(x0, z0, P0, r0);
        STAGE2(x1, z1, P1, r1);
    }
    { // tail class 18
        u64 x0, z0, P0, Q0;
        STAGE1(x0, z0, P0, Q0, 18);
        u64 r0 = rcp_2(Q0);
        zp   = f2mul(zp, z0);
        Pacc = f2mul(Pacc, P0);
        float pl, ph, zl, zh;
        upk2(Pacc, pl, ph);
        lgp_lo += lg2f_(pl); lgp_hi += lg2f_(ph);
        upk2(zp, zl, zh);
        lgz_lo += lg2f_(zl); lgz_hi += lg2f_(zh);
        STAGE2(x0, z0, P0, r0);
    }
#undef STAGE1
#undef STAGE2

    float aP_lo, aP_hi, a2_lo, a2_hi, a0_lo, a0_hi;
    upk2(accP, aP_lo, aP_hi);
    upk2(acc2, a2_lo, a2_hi);
    upk2(a0v,  a0_lo, a0_hi);

    // sum_c g = LN2*lgp - 2.5*LN2*lgz - accP + acc2 + (a0 + 38) - 19*(2.5 + C)
    const float KADD = 38.0f - 19.0f * (2.5f + HALF_LN_2PI);

    float xa0 = ex2f(pa0 * LOG2EF);
    float xa1 = ex2f(pa1 * LOG2EF);

    float sumg_lo = fmaf(LN2F, lgp_lo, fmaf(-2.5f * LN2F, lgz_lo, a2_lo - aP_lo)) + a0_lo + KADD;
    float psi0_lo, lg0_lo;
    psi_lg_s(a0_lo, psi0_lo, lg0_lo);
    float kl_lo   = fmaf(-(a0_lo - 19.0f), psi0_lo, lg0_lo) + sumg_lo;
    float loss_lo = fmaf(0.01f, kl_lo, psi0_lo - psi_s(xa0));
    if (ig0) loss_lo = 0.0f;

    float sumg_hi = fmaf(LN2F, lgp_hi, fmaf(-2.5f * LN2F, lgz_hi, a2_hi - aP_hi)) + a0_hi + KADD;
    float psi0_hi, lg0_hi;
    psi_lg_s(a0_hi, psi0_hi, lg0_hi);
    float kl_hi   = fmaf(-(a0_hi - 19.0f), psi0_hi, lg0_hi) + sumg_hi;
    float loss_hi = fmaf(0.01f, kl_hi, psi0_hi - psi_s(xa1));
    if (ig1) loss_hi = 0.0f;

    float loss  = loss_lo + loss_hi;
    int   valid = (ig0 ? 0 : 1) + (ig1 ? 0 : 1);

#pragma unroll
    for (int o = 16; o; o >>= 1) {
        loss  += __shfl_down_sync(0xffffffffu, loss, o);
        valid += __shfl_down_sync(0xffffffffu, valid, o);
    }

    __shared__ float s_l[8];
    __shared__ int   s_v[8];
    int wid = threadIdx.x >> 5;
    int lid = threadIdx.x & 31;
    if (lid == 0) { s_l[wid] = loss; s_v[wid] = valid; }
    __syncthreads();

    if (threadIdx.x == 0) {
        float L = 0.0f;
        int   V = 0;
#pragma unroll
        for (int w = 0; w < 8; ++w) { L += s_l[w]; V += s_v[w]; }
        atomicAdd(&g_sum, (double)L);
        atomicAdd(&g_cnt, (unsigned long long)V);
        __threadfence();
        unsigned int n = atomicAdd(&g_arrive, 1u);
        if (n == (unsigned int)(NBLK_ - 1)) {
            __threadfence();
            double s = *((volatile double*)&g_sum);
            unsigned long long c = *((volatile unsigned long long*)&g_cnt);
            out[0] = (float)(s / (double)c);
            g_sum    = 0.0;
            g_cnt    = 0ull;
            g_arrive = 0u;
        }
    }
}

extern "C" void kernel_launch(void* const* d_in, const int* in_sizes, int n_in,
                              void* d_out, int out_size) {
    const float* pred = (const float*)d_in[0];
    const int*   tgt  = (const int*)d_in[1];
    float*       out  = (float*)d_out;

    bml_main<<<NBLK_, 256>>>(pred, tgt, out);
}